// round 6
// baseline (speedup 1.0000x reference)
#include <cuda_runtime.h>
#include <cstdint>

// Problem constants (from reference): V=100000 vocab, D=128 dim
#define VOCAB 100000
#define DIM4  32   // 128 floats = 32 float4
#define RES_BIT (1u << 30)

// Scratch: vocab -> candidate residual row. Validated in gather via
// ridx[row] == v, so no -1 fill pass is needed.
__device__ int g_remap[VOCAB];

__global__ void scatter_remap_kernel(const int* __restrict__ ridx, int R) {
    int i = blockIdx.x * blockDim.x + threadIdx.x;
    if (i < R) {
        g_remap[ridx[i]] = i;
    }
}

// Each warp owns 32 tokens.
// Phase 1: lane t resolves token t's index chain (3 coalesced LDGs, MLP=32).
// Phase 2: copy loop, 4 tokens per stage (4 independent LDG.128 in flight),
//          each lane moves one float4 per token. Streaming stores keep the
//          embedding tables resident in L2 (reads are 100% L2-hit).
__global__ __launch_bounds__(256)
void gather_kernel(const int* __restrict__ x,
                   const int* __restrict__ ridx,     // [R] sorted, L2-hot
                   const float4* __restrict__ pre,   // [V, 32] float4
                   const float4* __restrict__ res,   // [R, 32] float4
                   float4* __restrict__ out,         // [n_tok, 32] float4
                   int n_tok, int R) {
    int warp = (blockIdx.x * blockDim.x + threadIdx.x) >> 5;
    int lane = threadIdx.x & 31;
    long long base = (long long)warp * 32;
    if (base >= n_tok) return;

    // ---- Phase 1: per-lane index resolution (parallel across 32 tokens) ----
    long long mytok = base + lane;
    int v = (mytok < n_tok) ? __ldg(x + mytok) : 0;
    int r = g_remap[v];
    bool use_res = (r >= 0) && (r < R) && (__ldg(ridx + r) == v);
    // pack: bit30 = residual flag, low bits = row index (fits: V<2^17)
    unsigned packed = use_res ? ((unsigned)r | RES_BIT) : (unsigned)v;

    // ---- Phase 2: copy 32 rows, 4 at a time for MLP ----
    #pragma unroll
    for (int t0 = 0; t0 < 32; t0 += 4) {
        float4 val[4];
        #pragma unroll
        for (int k = 0; k < 4; k++) {
            unsigned p = __shfl_sync(0xFFFFFFFFu, packed, t0 + k);
            const float4* srow = (p & RES_BIT)
                               ? (res + (long long)(p & ~RES_BIT) * DIM4)
                               : (pre + (long long)p * DIM4);
            val[k] = __ldg(srow + lane);
        }
        #pragma unroll
        for (int k = 0; k < 4; k++) {
            long long tok = base + t0 + k;
            if (tok < n_tok)
                __stcs(out + tok * DIM4 + lane, val[k]);
        }
    }
}

extern "C" void kernel_launch(void* const* d_in, const int* in_sizes, int n_in,
                              void* d_out, int out_size) {
    // Input order per reference setup_inputs():
    //   0: x                    [B*S]   int32
    //   1: residual_index       [R]     int32
    //   2: pretrained_embedding [V*D]   float32
    //   3: residual_embedding   [R*D]   float32
    const int*    x    = (const int*)d_in[0];
    const int*    ridx = (const int*)d_in[1];
    const float4* pre  = (const float4*)d_in[2];
    const float4* res  = (const float4*)d_in[3];
    float4*       out  = (float4*)d_out;

    const int n_tok = in_sizes[0];          // B*S = 262144
    const int R     = in_sizes[1];          // 20000

    scatter_remap_kernel<<<(R + 127) / 128, 128>>>(ridx, R);

    const long long n_warps = ((long long)n_tok + 31) / 32;   // 32 tokens per warp
    const long long total_threads = n_warps * 32;
    const int block = 256;
    const int grid  = (int)((total_threads + block - 1) / block);
    gather_kernel<<<grid, block>>>(x, ridx, pre, res, out, n_tok, R);
}